// round 2
// baseline (speedup 1.0000x reference)
#include <cuda_runtime.h>
#include <cstdint>

#define VN 10000
#define RN 5
#define AN 8
#define CN 64
#define TN 64
#define KN (RN*AN*CN)   /* 2560 */
#define NNW (AN*TN)     /* 512  */
#define NCHUNK (KN/16)  /* 160  */

// Scratch (device globals: no allocations allowed in kernel_launch)
__device__ float g_X [(size_t)VN * KN];   // interp result, both stages (102.4 MB)
__device__ float g_B1[KN * NNW];          // rotated templates1 (5.2 MB)
__device__ float g_B2[KN * NNW];          // rotated templates2 (5.2 MB)
__device__ float g_Y1[VN * CN];           // stage-1 output (2.56 MB)

// ---------------------------------------------------------------------------
// Build Brot[k=(r,a,c)][n=(o,t)] = T[t, r, (o+a)%A, c] for both templates.
// ---------------------------------------------------------------------------
__global__ void prep_rot_kernel(const float* __restrict__ T1,
                                const float* __restrict__ T2) {
    int i = blockIdx.x * blockDim.x + threadIdx.x;
    const int total = KN * NNW;
    const float* Tm; float* B; int e;
    if (i < total) { Tm = T1; B = g_B1; e = i; }
    else           { Tm = T2; B = g_B2; e = i - total; }
    int k = e / NNW, n = e - k * NNW;
    int c = k & 63; int ra = k >> 6; int a = ra & 7; int r = ra >> 3;
    int t = n & 63; int o = n >> 6;
    int ap = (o + a) & 7;
    B[e] = Tm[((t * RN + r) * AN + ap) * CN + c];
}

// ---------------------------------------------------------------------------
// interp: X[v, (r,a), c] = sum_{i<3} bc_w[v,r,a,i] * src[bc_idx[v,r,a,i], c]
// One thread per (v,r,a, c/4) quad. src = signal (stage1) or g_Y1 (stage2).
// ---------------------------------------------------------------------------
__global__ void interp_kernel(const float* __restrict__ src_ext,
                              const int*   __restrict__ bc_idx,
                              const float* __restrict__ bc_w,
                              int use_y1) {
    const float* src = use_y1 ? (const float*)g_Y1 : src_ext;
    int i = blockIdx.x * blockDim.x + threadIdx.x;  // exactly V*R*A*16 threads
    int q = i & 15;
    int g = i >> 4;                                 // (v*R + r)*A + a
    int i0 = bc_idx[g*3+0], i1 = bc_idx[g*3+1], i2 = bc_idx[g*3+2];
    float w0 = bc_w[g*3+0],  w1 = bc_w[g*3+1],  w2 = bc_w[g*3+2];
    float4 x0 = ((const float4*)(src + (size_t)i0 * CN))[q];
    float4 x1 = ((const float4*)(src + (size_t)i1 * CN))[q];
    float4 x2 = ((const float4*)(src + (size_t)i2 * CN))[q];
    float4 r;
    r.x = w0*x0.x + w1*x1.x + w2*x2.x;
    r.y = w0*x0.y + w1*x1.y + w2*x2.y;
    r.z = w0*x0.z + w1*x1.z + w2*x2.z;
    r.w = w0*x0.w + w1*x1.w + w2*x2.w;
    ((float4*)g_X)[(size_t)g * 16 + q] = r;   // X[v*KN + ra*64 + q*4]
}

// ---------------------------------------------------------------------------
// cp.async helpers
// ---------------------------------------------------------------------------
__device__ __forceinline__ void cpa16(uint32_t dst, const void* src) {
    asm volatile("cp.async.ca.shared.global [%0], [%1], 16;\n" :: "r"(dst), "l"(src));
}
__device__ __forceinline__ void cp_commit() {
    asm volatile("cp.async.commit_group;\n" ::);
}
template<int N> __device__ __forceinline__ void cp_wait() {
    asm volatile("cp.async.wait_group %0;\n" :: "n"(N));
}

#define FMA4(ACC, A_, B_)                                   \
    ACC.x = fmaf(A_, B_.x, ACC.x);                          \
    ACC.y = fmaf(A_, B_.y, ACC.y);                          \
    ACC.z = fmaf(A_, B_.z, ACC.z);                          \
    ACC.w = fmaf(A_, B_.w, ACC.w);

// ---------------------------------------------------------------------------
// GEMM (M=V, N=512, K=2560) + fused bias + angular argmax-pool + BN (+resid)
// + relu. CTA tile 32(m) x 512(n). 8 warps; warp w owns m = v0 + 4w .. +3,
// all 512 n. Thread (lane) owns n = lane*4 + q*128, q=0..3
//   -> o = lane/16 + 2q, t = (lane%16)*4 + j.  Pooling is warp-local shfl.
// ---------------------------------------------------------------------------
template<bool STAGE2>
__global__ void __launch_bounds__(256, 2)
gemm_pool_kernel(const float* __restrict__ bias,
                 const float* __restrict__ gamma,
                 const float* __restrict__ beta,
                 const float* __restrict__ resid,
                 float* __restrict__ outp) {
    extern __shared__ float smem[];
    float* As = smem;           // [2][32][16]   (m-major rows of 16 k)
    float* Bs = smem + 1024;    // [2][16][512]
    const float* X = g_X;
    const float* B = STAGE2 ? g_B2 : g_B1;
    float* out = STAGE2 ? outp : g_Y1;

    const int tid  = threadIdx.x;
    const int warp = tid >> 5, lane = tid & 31;
    const int v0   = blockIdx.x * 32;
    const uint32_t s_as = (uint32_t)__cvta_generic_to_shared(As);
    const uint32_t s_bs = (uint32_t)__cvta_generic_to_shared(Bs);

    float4 acc[4][4];
    #pragma unroll
    for (int mi = 0; mi < 4; mi++)
        #pragma unroll
        for (int q = 0; q < 4; q++)
            acc[mi][q] = make_float4(0.f, 0.f, 0.f, 0.f);

    auto issue = [&](int ck) {
        const int buf = ck & 1;
        const int k0  = ck * 16;
        // B tile: contiguous 32KB starting at B + k0*512
        const float* bsrc = B + (size_t)k0 * NNW + tid * 4;
        uint32_t bdst = s_bs + (uint32_t)buf * (16 * 512 * 4) + tid * 16;
        #pragma unroll
        for (int j = 0; j < 8; j++)
            cpa16(bdst + j * 4096, bsrc + j * 1024);
        // A tile: 32 rows x 16 k, threads 0..127 copy one float4 each
        if (tid < 128) {
            int m = tid >> 2, kq = (tid & 3) << 2;
            int v = v0 + m; if (v >= VN) v = VN - 1;   // clamp (never stored)
            cpa16(s_as + (uint32_t)(buf * 512 + m * 16 + kq) * 4,
                  X + (size_t)v * KN + k0 + kq);
        }
        cp_commit();
    };

    issue(0);
    for (int i = 0; i < NCHUNK; i++) {
        const int buf = i & 1;
        if (i + 1 < NCHUNK) { issue(i + 1); cp_wait<1>(); }
        else                { cp_wait<0>(); }
        __syncthreads();
        const float*  Ab = As + buf * 512 + warp * 64;      // 4 rows of 16
        const float4* Bb = (const float4*)(Bs + buf * 8192);
        #pragma unroll
        for (int kk = 0; kk < 16; kk++) {
            float a0 = Ab[kk], a1 = Ab[16 + kk], a2 = Ab[32 + kk], a3 = Ab[48 + kk];
            #pragma unroll
            for (int q = 0; q < 4; q++) {
                float4 b = Bb[kk * 128 + q * 32 + lane];
                FMA4(acc[0][q], a0, b);
                FMA4(acc[1][q], a1, b);
                FMA4(acc[2][q], a2, b);
                FMA4(acc[3][q], a3, b);
            }
        }
        __syncthreads();
    }

    // ---------------- epilogue: bias, argmax-pool over o, BN, (resid), relu
    const int tq = lane & 15;        // t-quad index: t = tq*4 + j
    const int h  = lane >> 4;        // o parity owned by this lane
    const float inv = rsqrtf(1.0f + 0.001f);
    const float4 biasv = ((const float4*)bias )[tq];
    const float4 gv    = ((const float4*)gamma)[tq];
    const float4 bv    = ((const float4*)beta )[tq];

    #pragma unroll
    for (int mi = 0; mi < 4; mi++) {
        const int m = v0 + warp * 4 + mi;
        #pragma unroll
        for (int q = 0; q < 4; q++) {
            acc[mi][q].x += biasv.x; acc[mi][q].y += biasv.y;
            acc[mi][q].z += biasv.z; acc[mi][q].w += biasv.w;
        }
        // per-(m,o) sum of squares; o = h + 2q lives across 16 lanes (tq)
        float p[4];
        #pragma unroll
        for (int q = 0; q < 4; q++) {
            float4 s = acc[mi][q];
            p[q] = s.x*s.x + s.y*s.y + s.z*s.z + s.w*s.w;
        }
        #pragma unroll
        for (int sft = 1; sft < 16; sft <<= 1)
            #pragma unroll
            for (int q = 0; q < 4; q++)
                p[q] += __shfl_xor_sync(0xffffffffu, p[q], sft);
        // local argmax among this half's o = h, h+2, h+4, h+6 (first max wins)
        float best = p[0]; int bo = h;
        #pragma unroll
        for (int q = 1; q < 4; q++) {
            if (p[q] > best) { best = p[q]; bo = h + 2 * q; }
        }
        // combine with other parity half; tie -> smaller o (matches argmax)
        float ob = __shfl_xor_sync(0xffffffffu, best, 16);
        int   oo = __shfl_xor_sync(0xffffffffu, bo,   16);
        if (ob > best || (ob == best && oo < bo)) { best = ob; bo = oo; }

        if (m < VN && h == (bo & 1)) {
            float4 val = acc[mi][bo >> 1];
            val.x = gv.x * (val.x * inv) + bv.x;
            val.y = gv.y * (val.y * inv) + bv.y;
            val.z = gv.z * (val.z * inv) + bv.z;
            val.w = gv.w * (val.w * inv) + bv.w;
            if (STAGE2) {
                float4 rs = ((const float4*)resid)[(size_t)m * 16 + tq];
                val.x += rs.x; val.y += rs.y; val.z += rs.z; val.w += rs.w;
            }
            val.x = fmaxf(val.x, 0.f); val.y = fmaxf(val.y, 0.f);
            val.z = fmaxf(val.z, 0.f); val.w = fmaxf(val.w, 0.f);
            ((float4*)out)[(size_t)m * 16 + tq] = val;
        }
    }
}

// ---------------------------------------------------------------------------
extern "C" void kernel_launch(void* const* d_in, const int* in_sizes, int n_in,
                              void* d_out, int out_size) {
    const float* signal = (const float*)d_in[0];
    const float* bc_w   = (const float*)d_in[1];
    const float* t1     = (const float*)d_in[2];
    const float* bias1  = (const float*)d_in[3];
    const float* gamma1 = (const float*)d_in[4];
    const float* beta1  = (const float*)d_in[5];
    const float* t2     = (const float*)d_in[6];
    const float* bias2  = (const float*)d_in[7];
    const float* gamma2 = (const float*)d_in[8];
    const float* beta2  = (const float*)d_in[9];
    const int*   bc_idx = (const int*)d_in[10];
    float* out = (float*)d_out;

    const int smem_bytes = (1024 + 2 * 16 * 512) * 4;  // 69632
    cudaFuncSetAttribute(gemm_pool_kernel<false>,
                         cudaFuncAttributeMaxDynamicSharedMemorySize, smem_bytes);
    cudaFuncSetAttribute(gemm_pool_kernel<true>,
                         cudaFuncAttributeMaxDynamicSharedMemorySize, smem_bytes);

    const int gemm_grid = (VN + 31) / 32;  // 313

    prep_rot_kernel<<<(2 * KN * NNW) / 256, 256>>>(t1, t2);
    interp_kernel<<<(VN * RN * AN * 16) / 256, 256>>>(signal, bc_idx, bc_w, 0);
    gemm_pool_kernel<false><<<gemm_grid, 256, smem_bytes>>>(
        bias1, gamma1, beta1, nullptr, out);
    interp_kernel<<<(VN * RN * AN * 16) / 256, 256>>>(nullptr, bc_idx, bc_w, 1);
    gemm_pool_kernel<true><<<gemm_grid, 256, smem_bytes>>>(
        bias2, gamma2, beta2, signal, out);
}

// round 3
// speedup vs baseline: 1.2715x; 1.2715x over previous
#include <cuda_runtime.h>
#include <cstdint>

#define VN 10000
#define RN 5
#define AN 8
#define CN 64
#define TN 64
#define KN 2560        /* R*A*C */
#define NNW 512        /* A*T   */
#define KCH 16
#define NCHUNK (KN/KCH)  /* 160 */

// Scratch (device globals: no allocation allowed in kernel_launch)
__device__ float g_Xh[(size_t)VN * KN];   // interp result, tf32-hi (102 MB)
__device__ float g_Xl[(size_t)VN * KN];   // interp result, tf32-lo (102 MB)
__device__ float g_B1h[NNW * KN];         // BT1 hi  [n][k] (5.2 MB)
__device__ float g_B1l[NNW * KN];
__device__ float g_B2h[NNW * KN];
__device__ float g_B2l[NNW * KN];
__device__ float g_S [(size_t)VN * NNW];  // GEMM output, pre-pool (20.5 MB)
__device__ float g_Y1[VN * CN];           // stage-1 output (2.56 MB)

__device__ __forceinline__ float tf32r(float x) {
    uint32_t u; asm("cvt.rna.tf32.f32 %0, %1;" : "=r"(u) : "f"(x));
    return __uint_as_float(u);
}

// ---------------------------------------------------------------------------
// Build BT[n=(o,t)][k=(r,a,c)] = T[t, r, (o+a)%A, c], split into tf32 hi/lo.
// ---------------------------------------------------------------------------
__global__ void prep_rot_kernel(const float* __restrict__ T1,
                                const float* __restrict__ T2) {
    int i = blockIdx.x * blockDim.x + threadIdx.x;
    const int total = NNW * KN;
    const float* Tm; float *Bh, *Bl; int e;
    if (i < total) { Tm = T1; Bh = g_B1h; Bl = g_B1l; e = i; }
    else           { Tm = T2; Bh = g_B2h; Bl = g_B2l; e = i - total; }
    int n = e / KN, k = e - n * KN;
    int c = k & 63; int ra = k >> 6; int a = ra & 7; int r = ra >> 3;
    int t = n & 63; int o = n >> 6;
    float v = Tm[((t * RN + r) * AN + ((o + a) & 7)) * CN + c];
    float h = tf32r(v);
    Bh[e] = h;
    Bl[e] = tf32r(v - h);
}

// ---------------------------------------------------------------------------
// interp: X[v,(r,a),c] = sum_i w_i * src[idx_i, c]; writes tf32 hi/lo split.
// ---------------------------------------------------------------------------
__global__ void interp_kernel(const float* __restrict__ src_ext,
                              const int*   __restrict__ bc_idx,
                              const float* __restrict__ bc_w,
                              int use_y1) {
    const float* src = use_y1 ? (const float*)g_Y1 : src_ext;
    int i = blockIdx.x * blockDim.x + threadIdx.x;  // V*R*A*16 threads
    int q = i & 15;
    int g = i >> 4;
    int i0 = bc_idx[g*3+0], i1 = bc_idx[g*3+1], i2 = bc_idx[g*3+2];
    float w0 = bc_w[g*3+0],  w1 = bc_w[g*3+1],  w2 = bc_w[g*3+2];
    float4 x0 = ((const float4*)(src + (size_t)i0 * CN))[q];
    float4 x1 = ((const float4*)(src + (size_t)i1 * CN))[q];
    float4 x2 = ((const float4*)(src + (size_t)i2 * CN))[q];
    float4 r;
    r.x = w0*x0.x + w1*x1.x + w2*x2.x;
    r.y = w0*x0.y + w1*x1.y + w2*x2.y;
    r.z = w0*x0.z + w1*x1.z + w2*x2.z;
    r.w = w0*x0.w + w1*x1.w + w2*x2.w;
    float4 h, l;
    h.x = tf32r(r.x); l.x = tf32r(r.x - h.x);
    h.y = tf32r(r.y); l.y = tf32r(r.y - h.y);
    h.z = tf32r(r.z); l.z = tf32r(r.z - h.z);
    h.w = tf32r(r.w); l.w = tf32r(r.w - h.w);
    ((float4*)g_Xh)[(size_t)g * 16 + q] = h;
    ((float4*)g_Xl)[(size_t)g * 16 + q] = l;
}

// ---------------------------------------------------------------------------
// cp.async helpers
// ---------------------------------------------------------------------------
__device__ __forceinline__ void cpa16(uint32_t dst, const void* src) {
    asm volatile("cp.async.ca.shared.global [%0], [%1], 16;\n" :: "r"(dst), "l"(src));
}
__device__ __forceinline__ void cp_commit() {
    asm volatile("cp.async.commit_group;\n" ::);
}
template<int N> __device__ __forceinline__ void cp_wait() {
    asm volatile("cp.async.wait_group %0;\n" :: "n"(N));
}

__device__ __forceinline__ void mma_tf32(float* d, const uint32_t* a, const uint32_t* b) {
    asm volatile(
        "mma.sync.aligned.m16n8k8.row.col.f32.tf32.tf32.f32 "
        "{%0,%1,%2,%3}, {%4,%5,%6,%7}, {%8,%9}, {%0,%1,%2,%3};\n"
        : "+f"(d[0]), "+f"(d[1]), "+f"(d[2]), "+f"(d[3])
        : "r"(a[0]), "r"(a[1]), "r"(a[2]), "r"(a[3]), "r"(b[0]), "r"(b[1]));
}

// ---------------------------------------------------------------------------
// 3xTF32 GEMM: S[v][n] = X[v][k] * BT[n][k]^T.  CTA 64m x 256n, 256 threads,
// 8 warps in 2(m) x 4(n) grid; warp tile 32m x 64n = 2 x 8 mma frags.
// K chunked by 16, cp.async double-buffered. smem rows padded to 20 floats.
// ---------------------------------------------------------------------------
__global__ void __launch_bounds__(256, 2)
gemm_kernel(const float* __restrict__ Bh_g, const float* __restrict__ Bl_g) {
    extern __shared__ float sm[];
    float* sAh = sm;                      // [2][64*20]
    float* sAl = sm + 2 * 1280;
    float* sBh = sm + 4 * 1280;           // [2][256*20]
    float* sBl = sm + 4 * 1280 + 2 * 5120;

    const int tid  = threadIdx.x;
    const int warp = tid >> 5, lane = tid & 31;
    const int wm = warp >> 2, wn = warp & 3;       // 2 x 4 warp grid
    const int m0 = blockIdx.x * 64;
    const int n0 = blockIdx.y * 256;

    const uint32_t s_ah = (uint32_t)__cvta_generic_to_shared(sAh);
    const uint32_t s_al = (uint32_t)__cvta_generic_to_shared(sAl);
    const uint32_t s_bh = (uint32_t)__cvta_generic_to_shared(sBh);
    const uint32_t s_bl = (uint32_t)__cvta_generic_to_shared(sBl);

    float acc[2][8][4];
    #pragma unroll
    for (int mi = 0; mi < 2; mi++)
        #pragma unroll
        for (int ni = 0; ni < 8; ni++)
            #pragma unroll
            for (int j = 0; j < 4; j++) acc[mi][ni][j] = 0.f;

    auto issue = [&](int ck) {
        const int buf = ck & 1;
        const int k0  = ck * KCH;
        // A: 64 rows x 16 k, 256 segs of 4 floats -> 1 per thread per half
        {
            int row = tid >> 2, kq = (tid & 3) << 2;
            int v = m0 + row; if (v >= VN) v = VN - 1;     // clamp (dropped at store)
            size_t go = (size_t)v * KN + k0 + kq;
            uint32_t doff = (uint32_t)(buf * 1280 + row * 20 + kq) * 4;
            cpa16(s_ah + doff, g_Xh + go);
            cpa16(s_al + doff, g_Xl + go);
        }
        // B: 256 rows x 16 k -> 1024 segs per half -> 4 per thread
        #pragma unroll
        for (int j = 0; j < 4; j++) {
            int seg = tid + j * 256;
            int row = seg >> 2, kq = (seg & 3) << 2;
            size_t go = (size_t)(n0 + row) * KN + k0 + kq;
            uint32_t doff = (uint32_t)(buf * 5120 + row * 20 + kq) * 4;
            cpa16(s_bh + doff, Bh_g + go);
            cpa16(s_bl + doff, Bl_g + go);
        }
        cp_commit();
    };

    issue(0);
    for (int i = 0; i < NCHUNK; i++) {
        const int buf = i & 1;
        if (i + 1 < NCHUNK) { issue(i + 1); cp_wait<1>(); }
        else                { cp_wait<0>(); }
        __syncthreads();
        const float* Ah = sAh + buf * 1280;
        const float* Al = sAl + buf * 1280;
        const float* Bh = sBh + buf * 5120;
        const float* Bl = sBl + buf * 5120;
        #pragma unroll
        for (int ks = 0; ks < 2; ks++) {
            const int kc = ks * 8 + (lane & 3);
            uint32_t bh[8][2], bl[8][2];
            #pragma unroll
            for (int ni = 0; ni < 8; ni++) {
                int br = (wn * 64 + ni * 8 + (lane >> 2)) * 20 + kc;
                bh[ni][0] = __float_as_uint(Bh[br]);
                bh[ni][1] = __float_as_uint(Bh[br + 4]);
                bl[ni][0] = __float_as_uint(Bl[br]);
                bl[ni][1] = __float_as_uint(Bl[br + 4]);
            }
            #pragma unroll
            for (int mi = 0; mi < 2; mi++) {
                int ar = (wm * 32 + mi * 16 + (lane >> 2)) * 20 + kc;
                uint32_t ah[4], al[4];
                ah[0] = __float_as_uint(Ah[ar]);       ah[1] = __float_as_uint(Ah[ar + 160]);
                ah[2] = __float_as_uint(Ah[ar + 4]);   ah[3] = __float_as_uint(Ah[ar + 164]);
                al[0] = __float_as_uint(Al[ar]);       al[1] = __float_as_uint(Al[ar + 160]);
                al[2] = __float_as_uint(Al[ar + 4]);   al[3] = __float_as_uint(Al[ar + 164]);
                #pragma unroll
                for (int ni = 0; ni < 8; ni++) {
                    mma_tf32(acc[mi][ni], ah, bh[ni]);
                    mma_tf32(acc[mi][ni], al, bh[ni]);
                    mma_tf32(acc[mi][ni], ah, bl[ni]);
                }
            }
        }
        __syncthreads();
    }

    // Store raw S (pool kernel handles bias/argmax/BN/relu)
    const int gr  = lane >> 2;
    const int gc2 = (lane & 3) * 2;
    #pragma unroll
    for (int mi = 0; mi < 2; mi++) {
        int v = m0 + wm * 32 + mi * 16 + gr;
        #pragma unroll
        for (int ni = 0; ni < 8; ni++) {
            int n = n0 + wn * 64 + ni * 8 + gc2;
            if (v < VN)
                *(float2*)&g_S[(size_t)v * NNW + n] =
                    make_float2(acc[mi][ni][0], acc[mi][ni][1]);
            if (v + 8 < VN)
                *(float2*)&g_S[(size_t)(v + 8) * NNW + n] =
                    make_float2(acc[mi][ni][2], acc[mi][ni][3]);
        }
    }
}

// ---------------------------------------------------------------------------
// pool: bias -> norm argmax over o -> BN -> (resid) -> relu. One block per v,
// 64 threads (t). S[v][o*64+t].
// ---------------------------------------------------------------------------
template<bool STAGE2>
__global__ void pool_kernel(const float* __restrict__ bias,
                            const float* __restrict__ gamma,
                            const float* __restrict__ beta,
                            const float* __restrict__ resid,
                            float* __restrict__ out) {
    const int v = blockIdx.x, t = threadIdx.x;
    __shared__ float ssum[2][8];
    const float* Sv = g_S + (size_t)v * NNW;
    const float b = bias[t];
    float val[8], q[8];
    #pragma unroll
    for (int o = 0; o < 8; o++) {
        val[o] = Sv[o * 64 + t] + b;
        q[o] = val[o] * val[o];
    }
    #pragma unroll
    for (int sft = 1; sft < 32; sft <<= 1)
        #pragma unroll
        for (int o = 0; o < 8; o++)
            q[o] += __shfl_xor_sync(0xffffffffu, q[o], sft);
    if ((t & 31) == 0) {
        #pragma unroll
        for (int o = 0; o < 8; o++) ssum[t >> 5][o] = q[o];
    }
    __syncthreads();
    float best = ssum[0][0] + ssum[1][0];
    int bo = 0;
    #pragma unroll
    for (int o = 1; o < 8; o++) {
        float s = ssum[0][o] + ssum[1][o];
        if (s > best) { best = s; bo = o; }   // first max wins (matches argmax)
    }
    const float INV = 0.999500373802f;        // rsqrt(1 + 1e-3) in fp32
    float y = gamma[t] * (val[bo] * INV) + beta[t];
    if (STAGE2) y += resid[v * 64 + t];
    y = fmaxf(y, 0.f);
    out[v * 64 + t] = y;
}

// ---------------------------------------------------------------------------
extern "C" void kernel_launch(void* const* d_in, const int* in_sizes, int n_in,
                              void* d_out, int out_size) {
    const float* signal = (const float*)d_in[0];
    const float* bc_w   = (const float*)d_in[1];
    const float* t1     = (const float*)d_in[2];
    const float* bias1  = (const float*)d_in[3];
    const float* gamma1 = (const float*)d_in[4];
    const float* beta1  = (const float*)d_in[5];
    const float* t2     = (const float*)d_in[6];
    const float* bias2  = (const float*)d_in[7];
    const float* gamma2 = (const float*)d_in[8];
    const float* beta2  = (const float*)d_in[9];
    const int*   bc_idx = (const int*)d_in[10];
    float* out = (float*)d_out;

    float *d_B1h, *d_B1l, *d_B2h, *d_B2l, *d_Y1;
    cudaGetSymbolAddress((void**)&d_B1h, g_B1h);
    cudaGetSymbolAddress((void**)&d_B1l, g_B1l);
    cudaGetSymbolAddress((void**)&d_B2h, g_B2h);
    cudaGetSymbolAddress((void**)&d_B2l, g_B2l);
    cudaGetSymbolAddress((void**)&d_Y1,  g_Y1);

    const int smem_bytes = 25600 * 4;   // 102400
    cudaFuncSetAttribute(gemm_kernel,
                         cudaFuncAttributeMaxDynamicSharedMemorySize, smem_bytes);

    dim3 ggrid(157, 2);                 // 64m x 256n tiles

    prep_rot_kernel<<<(2 * NNW * KN) / 256, 256>>>(t1, t2);
    interp_kernel<<<(VN * RN * AN * 16) / 256, 256>>>(signal, bc_idx, bc_w, 0);
    gemm_kernel<<<ggrid, 256, smem_bytes>>>(d_B1h, d_B1l);
    pool_kernel<false><<<VN, 64>>>(bias1, gamma1, beta1, nullptr, d_Y1);
    interp_kernel<<<(VN * RN * AN * 16) / 256, 256>>>(nullptr, bc_idx, bc_w, 1);
    gemm_kernel<<<ggrid, 256, smem_bytes>>>(d_B2h, d_B2l);
    pool_kernel<true><<<VN, 64>>>(bias2, gamma2, beta2, signal, out);
}

// round 7
// speedup vs baseline: 4.7102x; 3.7044x over previous
#include <cuda_runtime.h>
#include <cuda_fp16.h>
#include <cstdint>

#define VN 10000
#define RN 5
#define AN 8
#define CN 64
#define TN 64
#define KN 2560        /* R*A*C */
#define NNW 512        /* A*T   */

#define MT 64
#define NT 128
#define KC 64                     /* k-halfs per chunk: 128B rows */
#define NITER (KN / KC)           /* 40 */
#define A_HALF_BYTES (MT * KC * 2)   /* 8192  */
#define B_HALF_BYTES (NT * KC * 2)   /* 16384 */
#define STAGE_BYTES (2 * A_HALF_BYTES + 2 * B_HALF_BYTES)  /* 49152 */

// Scratch (device globals: no allocations allowed)
__device__ __half g_Xh[(size_t)VN * KN];   // interp result, fp16-hi (51 MB)
__device__ __half g_Xl[(size_t)VN * KN];   // interp result, fp16-lo
__device__ __half g_B1h[NNW * KN];         // BT1 hi  [n][k] (2.6 MB)
__device__ __half g_B1l[NNW * KN];
__device__ __half g_B2h[NNW * KN];
__device__ __half g_B2l[NNW * KN];
__device__ float  g_S [(size_t)VN * NNW];  // GEMM output, pre-pool (20.5 MB)
__device__ float  g_Y1[VN * CN];           // stage-1 output

// ---------------------------------------------------------------------------
// helpers
// ---------------------------------------------------------------------------
__device__ __forceinline__ uint32_t smem_u32(const void* p) {
    uint32_t a;
    asm("{ .reg .u64 t; cvta.to.shared.u64 t, %1; cvt.u32.u64 %0, t; }"
        : "=r"(a) : "l"(p));
    return a;
}
__device__ __forceinline__ void cpa16(uint32_t dst, const void* src) {
    asm volatile("cp.async.ca.shared.global [%0], [%1], 16;\n" :: "r"(dst), "l"(src));
}
__device__ __forceinline__ void cp_commit() {
    asm volatile("cp.async.commit_group;\n" ::);
}
template<int N> __device__ __forceinline__ void cp_wait() {
    asm volatile("cp.async.wait_group %0;\n" :: "n"(N));
}
__device__ __forceinline__ void ldsm4(uint32_t* r, uint32_t addr) {
    asm volatile("ldmatrix.sync.aligned.m8n8.x4.shared.b16 {%0,%1,%2,%3}, [%4];"
                 : "=r"(r[0]), "=r"(r[1]), "=r"(r[2]), "=r"(r[3]) : "r"(addr));
}
__device__ __forceinline__ void hmma(float* d, const uint32_t* a, const uint32_t* b) {
    asm volatile(
        "mma.sync.aligned.m16n8k16.row.col.f32.f16.f16.f32 "
        "{%0,%1,%2,%3}, {%4,%5,%6,%7}, {%8,%9}, {%0,%1,%2,%3};\n"
        : "+f"(d[0]), "+f"(d[1]), "+f"(d[2]), "+f"(d[3])
        : "r"(a[0]), "r"(a[1]), "r"(a[2]), "r"(a[3]), "r"(b[0]), "r"(b[1]));
}
// swizzled offset within a tile: rows of 128B (8 x 16B chunks)
__device__ __forceinline__ uint32_t swz(int row, int c) {
    return (uint32_t)(row * 128 + ((c ^ (row & 7)) << 4));
}

// ---------------------------------------------------------------------------
// Build BT[n=(o,t)][k=(r,a,c)] = T[t, r, (o+a)%A, c], fp16 hi/lo split.
// ---------------------------------------------------------------------------
__global__ void prep_rot_kernel(const float* __restrict__ T1,
                                const float* __restrict__ T2) {
    int i = blockIdx.x * blockDim.x + threadIdx.x;
    const int total = NNW * KN;
    const float* Tm; __half *Bh, *Bl; int e;
    if (i < total) { Tm = T1; Bh = g_B1h; Bl = g_B1l; e = i; }
    else           { Tm = T2; Bh = g_B2h; Bl = g_B2l; e = i - total; }
    int n = e / KN, k = e - n * KN;
    int c = k & 63; int ra = k >> 6; int a = ra & 7; int r = ra >> 3;
    int t = n & 63; int o = n >> 6;
    float v = Tm[((t * RN + r) * AN + ((o + a) & 7)) * CN + c];
    __half h = __float2half_rn(v);
    Bh[e] = h;
    Bl[e] = __float2half_rn(v - __half2float(h));
}

// ---------------------------------------------------------------------------
// interp: X[v,(r,a),c] = sum_i w_i * src[idx_i, c]; fp16 hi/lo split output.
// ---------------------------------------------------------------------------
__global__ void interp_kernel(const float* __restrict__ src_ext,
                              const int*   __restrict__ bc_idx,
                              const float* __restrict__ bc_w,
                              int use_y1) {
    const float* src = use_y1 ? (const float*)g_Y1 : src_ext;
    int i = blockIdx.x * blockDim.x + threadIdx.x;  // V*R*A*16 threads
    int q = i & 15;
    int g = i >> 4;
    int i0 = bc_idx[g*3+0], i1 = bc_idx[g*3+1], i2 = bc_idx[g*3+2];
    float w0 = bc_w[g*3+0],  w1 = bc_w[g*3+1],  w2 = bc_w[g*3+2];
    float4 x0 = ((const float4*)(src + (size_t)i0 * CN))[q];
    float4 x1 = ((const float4*)(src + (size_t)i1 * CN))[q];
    float4 x2 = ((const float4*)(src + (size_t)i2 * CN))[q];
    float4 r;
    r.x = w0*x0.x + w1*x1.x + w2*x2.x;
    r.y = w0*x0.y + w1*x1.y + w2*x2.y;
    r.z = w0*x0.z + w1*x1.z + w2*x2.z;
    r.w = w0*x0.w + w1*x1.w + w2*x2.w;
    __half hx = __float2half_rn(r.x), hy = __float2half_rn(r.y);
    __half hz = __float2half_rn(r.z), hw = __float2half_rn(r.w);
    __half lx = __float2half_rn(r.x - __half2float(hx));
    __half ly = __float2half_rn(r.y - __half2float(hy));
    __half lz = __float2half_rn(r.z - __half2float(hz));
    __half lw = __float2half_rn(r.w - __half2float(hw));
    __half2 h01 = __halves2half2(hx, hy), h23 = __halves2half2(hz, hw);
    __half2 l01 = __halves2half2(lx, ly), l23 = __halves2half2(lz, lw);
    size_t off = (size_t)g * 64 + q * 4;
    uint2 hv = make_uint2(*(uint32_t*)&h01, *(uint32_t*)&h23);
    uint2 lv = make_uint2(*(uint32_t*)&l01, *(uint32_t*)&l23);
    *(uint2*)&g_Xh[off] = hv;
    *(uint2*)&g_Xl[off] = lv;
}

// ---------------------------------------------------------------------------
// fp16x3 GEMM via mma.sync.m16n8k16: S[v][n] = X[v][k] * BT[n][k]^T
// CTA 64m x 128n; 8 warps (2m x 4n), warp tile 32m x 32n.
// K chunks of 64 halfs; cp.async double-buffered; ldmatrix.x4 frags.
// ---------------------------------------------------------------------------
__global__ void __launch_bounds__(256, 2)
gemm_kernel(const __half* __restrict__ Bh_g, const __half* __restrict__ Bl_g) {
    extern __shared__ char dsm[];
    const uint32_t sb = smem_u32(dsm);
    // per stage: [Ah 8K][Al 8K][Bh 16K][Bl 16K]

    const int tid  = threadIdx.x;
    const int warp = tid >> 5, lane = tid & 31;
    const int wm = warp >> 2, wn = warp & 3;           // 2 x 4 warp grid
    const int m0 = blockIdx.x * MT;
    const int n0 = blockIdx.y * NT;

    float acc[2][4][4];
    #pragma unroll
    for (int mi = 0; mi < 2; mi++)
        #pragma unroll
        for (int ni = 0; ni < 4; ni++)
            #pragma unroll
            for (int j = 0; j < 4; j++) acc[mi][ni][j] = 0.f;

    auto issue = [&](int ck) {
        const int buf = ck & 1;
        const int k0  = ck * KC;
        const uint32_t st = sb + buf * STAGE_BYTES;
        // A: 64 rows x 8 chunks = 512 -> 2 per thread (hi+lo each)
        #pragma unroll
        for (int j = 0; j < 2; j++) {
            int id = tid + j * 256;
            int row = id >> 3, c = id & 7;
            int v = m0 + row; if (v >= VN) v = VN - 1;
            size_t gs = (size_t)v * KN + k0 + c * 8;
            uint32_t d = swz(row, c);
            cpa16(st + d,                g_Xh + gs);
            cpa16(st + A_HALF_BYTES + d, g_Xl + gs);
        }
        // B: 128 rows x 8 chunks = 1024 -> 4 per thread (hi+lo each)
        #pragma unroll
        for (int j = 0; j < 4; j++) {
            int id = tid + j * 256;
            int row = id >> 3, c = id & 7;
            size_t gs = (size_t)(n0 + row) * KN + k0 + c * 8;
            uint32_t d = swz(row, c);
            cpa16(st + 2 * A_HALF_BYTES + d,                Bh_g + gs);
            cpa16(st + 2 * A_HALF_BYTES + B_HALF_BYTES + d, Bl_g + gs);
        }
        cp_commit();
    };

    issue(0);
    for (int it = 0; it < NITER; it++) {
        const int buf = it & 1;
        if (it + 1 < NITER) { issue(it + 1); cp_wait<1>(); }
        else                { cp_wait<0>(); }
        __syncthreads();
        const uint32_t st  = sb + buf * STAGE_BYTES;
        const uint32_t sAh = st;
        const uint32_t sAl = st + A_HALF_BYTES;
        const uint32_t sBh = st + 2 * A_HALF_BYTES;
        const uint32_t sBl = st + 2 * A_HALF_BYTES + B_HALF_BYTES;

        #pragma unroll
        for (int ks = 0; ks < 4; ks++) {           // 4 k16-steps per chunk
            // A fragments: rows m0..; lanes 0-15 pick m rows, lanes/16 pick k8
            uint32_t ah[2][4], al[2][4];
            #pragma unroll
            for (int mi = 0; mi < 2; mi++) {
                int row = wm * 32 + mi * 16 + (lane & 15);
                int c   = ks * 2 + (lane >> 4);
                ldsm4(ah[mi], sAh + swz(row, c));
                ldsm4(al[mi], sAl + swz(row, c));
            }
            // B fragment pairs: nj covers ni=2nj, 2nj+1
            uint32_t bh[4][4], bl[4][4];
            #pragma unroll
            for (int nj = 0; nj < 2; nj++) {
                int row = wn * 32 + nj * 16 + ((lane >> 4) << 3) + (lane & 7);
                int c   = ks * 2 + ((lane >> 3) & 1);
                ldsm4(bh[nj], sBh + swz(row, c));
                ldsm4(bl[nj], sBl + swz(row, c));
            }
            #pragma unroll
            for (int mi = 0; mi < 2; mi++)
                #pragma unroll
                for (int nj = 0; nj < 2; nj++) {
                    hmma(acc[mi][2*nj],   ah[mi], &bh[nj][0]);
                    hmma(acc[mi][2*nj],   al[mi], &bh[nj][0]);
                    hmma(acc[mi][2*nj],   ah[mi], &bl[nj][0]);
                    hmma(acc[mi][2*nj+1], ah[mi], &bh[nj][2]);
                    hmma(acc[mi][2*nj+1], al[mi], &bh[nj][2]);
                    hmma(acc[mi][2*nj+1], ah[mi], &bl[nj][2]);
                }
        }
        __syncthreads();
    }

    // store raw S
    const int gr = lane >> 2, gc = (lane & 3) * 2;
    #pragma unroll
    for (int mi = 0; mi < 2; mi++) {
        int v = m0 + wm * 32 + mi * 16 + gr;
        #pragma unroll
        for (int ni = 0; ni < 4; ni++) {
            int n = n0 + wn * 32 + ni * 8 + gc;
            if (v < VN)
                *(float2*)&g_S[(size_t)v * NNW + n] =
                    make_float2(acc[mi][ni][0], acc[mi][ni][1]);
            if (v + 8 < VN)
                *(float2*)&g_S[(size_t)(v + 8) * NNW + n] =
                    make_float2(acc[mi][ni][2], acc[mi][ni][3]);
        }
    }
}

// ---------------------------------------------------------------------------
// pool: bias -> norm argmax over o -> BN -> (resid) -> relu. 1 block per v.
// ---------------------------------------------------------------------------
template<bool STAGE2>
__global__ void pool_kernel(const float* __restrict__ bias,
                            const float* __restrict__ gamma,
                            const float* __restrict__ beta,
                            const float* __restrict__ resid,
                            float* __restrict__ out) {
    const int v = blockIdx.x, t = threadIdx.x;
    __shared__ float ssum[2][8];
    const float* Sv = g_S + (size_t)v * NNW;
    const float b = bias[t];
    float val[8], q[8];
    #pragma unroll
    for (int o = 0; o < 8; o++) {
        val[o] = Sv[o * 64 + t] + b;
        q[o] = val[o] * val[o];
    }
    #pragma unroll
    for (int sft = 1; sft < 32; sft <<= 1)
        #pragma unroll
        for (int o = 0; o < 8; o++)
            q[o] += __shfl_xor_sync(0xffffffffu, q[o], sft);
    if ((t & 31) == 0) {
        #pragma unroll
        for (int o = 0; o < 8; o++) ssum[t >> 5][o] = q[o];
    }
    __syncthreads();
    float best = ssum[0][0] + ssum[1][0];
    int bo = 0;
    #pragma unroll
    for (int o = 1; o < 8; o++) {
        float s = ssum[0][o] + ssum[1][o];
        if (s > best) { best = s; bo = o; }   // first max wins
    }
    const float INV = 0.999500373802f;        // rsqrt(1 + 1e-3)
    float y = gamma[t] * (val[bo] * INV) + beta[t];
    if (STAGE2) y += resid[v * 64 + t];
    y = fmaxf(y, 0.f);
    out[v * 64 + t] = y;
}

// ---------------------------------------------------------------------------
extern "C" void kernel_launch(void* const* d_in, const int* in_sizes, int n_in,
                              void* d_out, int out_size) {
    const float* signal = (const float*)d_in[0];
    const float* bc_w   = (const float*)d_in[1];
    const float* t1     = (const float*)d_in[2];
    const float* bias1  = (const float*)d_in[3];
    const float* gamma1 = (const float*)d_in[4];
    const float* beta1  = (const float*)d_in[5];
    const float* t2     = (const float*)d_in[6];
    const float* bias2  = (const float*)d_in[7];
    const float* gamma2 = (const float*)d_in[8];
    const float* beta2  = (const float*)d_in[9];
    const int*   bc_idx = (const int*)d_in[10];
    float* out = (float*)d_out;

    void *pB1h, *pB1l, *pB2h, *pB2l, *pY1;
    cudaGetSymbolAddress(&pB1h, g_B1h);
    cudaGetSymbolAddress(&pB1l, g_B1l);
    cudaGetSymbolAddress(&pB2h, g_B2h);
    cudaGetSymbolAddress(&pB2l, g_B2l);
    cudaGetSymbolAddress(&pY1,  g_Y1);

    const int smem_bytes = 2 * STAGE_BYTES;   // 98304
    cudaFuncSetAttribute(gemm_kernel,
                         cudaFuncAttributeMaxDynamicSharedMemorySize, smem_bytes);

    dim3 ggrid((VN + MT - 1) / MT, NNW / NT);   // 157 x 4

    prep_rot_kernel<<<(2 * NNW * KN) / 256, 256>>>(t1, t2);
    interp_kernel<<<(VN * RN * AN * 16) / 256, 256>>>(signal, bc_idx, bc_w, 0);
    gemm_kernel<<<ggrid, 256, smem_bytes>>>((const __half*)pB1h, (const __half*)pB1l);
    pool_kernel<false><<<VN, 64>>>(bias1, gamma1, beta1, nullptr, (float*)pY1);
    interp_kernel<<<(VN * RN * AN * 16) / 256, 256>>>(nullptr, bc_idx, bc_w, 1);
    gemm_kernel<<<ggrid, 256, smem_bytes>>>((const __half*)pB2h, (const __half*)pB2l);
    pool_kernel<true><<<VN, 64>>>(bias2, gamma2, beta2, signal, out);
}